// round 7
// baseline (speedup 1.0000x reference)
#include <cuda_runtime.h>
#include <cstdint>
#include <math.h>

#define B_  8
#define C_  256
#define Hh  80
#define Ww  80
#define HW  6400
#define NPIX 51200
#define EPSF 1e-5f

#define KC 32
#define STAGES 4
#define TSTR 36                 // smem row stride in floats (144B): LDSM conflict-free
#define A_ST (128*TSTR*4)       // 18432 B per A stage
#define B_ST (256*TSTR*4)       // 36864 B per B stage
#define SMEM_BYTES (STAGES*(A_ST+B_ST))   // 221184 B

// ---------------- scratch ----------------
__device__ float g_xT [(size_t)NPIX*256];
__device__ float g_qkv[(size_t)NPIX*768];
__device__ float g_y2 [(size_t)NPIX*256];
__device__ float g_x1r[(size_t)NPIX*256];
__device__ float g_x1f[(size_t)NPIX*256];
__device__ float g_h  [(size_t)NPIX*512];
__device__ float g_w  [524288];

// ---------------- helpers ----------------
__device__ __forceinline__ float rna(float x){ float r; asm("cvt.rna.tf32.f32 %0, %1;" : "=f"(r) : "f"(x)); return r; }
__device__ __forceinline__ uint32_t s2u(const void* p){
    uint32_t a; asm("{ .reg .u64 t; cvta.to.shared.u64 t, %1; cvt.u32.u64 %0, t; }" : "=r"(a) : "l"(p)); return a;
}
#define CPA16(d,s) asm volatile("cp.async.cg.shared.global [%0], [%1], 16;" :: "r"(d), "l"(s))
#define CPCOMMIT() asm volatile("cp.async.commit_group;" ::: "memory")
#define CPWAIT(n)  asm volatile("cp.async.wait_group %0;" :: "n"(n) : "memory")
#define LDSM4(r0,r1,r2,r3,a) \
    asm volatile("ldmatrix.sync.aligned.m8n8.x4.shared.b16 {%0,%1,%2,%3}, [%4];" \
        : "=r"(r0), "=r"(r1), "=r"(r2), "=r"(r3) : "r"(a))

__device__ __forceinline__ void mma8(float* d, const uint32_t* a, uint32_t b0, uint32_t b1){
    asm volatile("mma.sync.aligned.m16n8k8.row.col.f32.tf32.tf32.f32 "
        "{%0,%1,%2,%3}, {%4,%5,%6,%7}, {%8,%9}, {%0,%1,%2,%3};"
        : "+f"(d[0]), "+f"(d[1]), "+f"(d[2]), "+f"(d[3])
        : "r"(a[0]), "r"(a[1]), "r"(a[2]), "r"(a[3]), "r"(b0), "r"(b1));
}

// ---------------- tf32 mma.sync GEMM, 128x256 tile, 4-stage single-sync ----------------
// MODE 0: y = acc + bias[n]                            -> qkv (Cstride 768)
// MODE 1: Cp = rna(acc+bias+resx), Cp2 = full          -> x1r / x1f  (resx = x[b][c][hw])
// MODE 2: y = rna(silu(acc*sc+sh))                     -> h   (Cstride 512)
// MODE 3: y = acc*sc+sh + res -> out[b][n][pixl]       (smem-staged transposed store)
template<int MODE>
__global__ __launch_bounds__(256, 1) void gemm_mma(
    const float* __restrict__ A, const float* __restrict__ Bw,
    float* __restrict__ Cp, float* __restrict__ Cp2, int Ktot, int Cstride,
    const float* __restrict__ bias, const float* __restrict__ res,
    const float* __restrict__ gg, const float* __restrict__ bb,
    const float* __restrict__ mm, const float* __restrict__ vv)
{
    extern __shared__ float smemf[];
    const uint32_t smem_b = s2u(smemf);

    const int tid  = threadIdx.x;
    const int wid  = tid >> 5;
    const int lane = tid & 31;
    const int wm   = wid & 1;         // 2 warps in M (64 rows each)
    const int wn   = wid >> 1;        // 4 warps in N (64 cols each)
    const int lr   = lane >> 2;
    const int lc   = lane & 3;
    const int m0   = blockIdx.y * 128;
    const int n0   = blockIdx.x * 256;

    // LDSM per-thread byte offsets within a stage
    const uint32_t aoff = (uint32_t)(((wm*64 + ((lane>>3)&1)*8 + (lane&7))*TSTR + (lane>>4)*4) * 4);
    const uint32_t boff = (uint32_t)(((wn*64 + (lane>>4)*8 + (lane&7))*TSTR + ((lane>>3)&1)*4) * 4);

    float d[4][8][4];
#pragma unroll
    for (int i = 0; i < 4; i++)
#pragma unroll
        for (int j = 0; j < 8; j++)
#pragma unroll
            for (int e = 0; e < 4; e++) d[i][j][e] = 0.f;

    const int nch = Ktot / KC;

    auto load = [&](int cc){
        const int s = cc % STAGES;
        const float* Ab = A + (size_t)m0 * Ktot + cc*KC;
        const uint32_t da = smem_b + s*A_ST;
#pragma unroll
        for (int t = 0; t < 4; t++){
            int i = tid + t*256;
            int r = i >> 3, c = i & 7;
            CPA16(da + r*TSTR*4 + c*16, (const void*)(Ab + (size_t)r*Ktot + c*4));
        }
        const float* Bb = Bw + (size_t)n0 * Ktot + cc*KC;
        const uint32_t db = smem_b + STAGES*A_ST + s*B_ST;
#pragma unroll
        for (int t = 0; t < 8; t++){
            int i = tid + t*256;
            int r = i >> 3, c = i & 7;
            CPA16(db + r*TSTR*4 + c*16, (const void*)(Bb + (size_t)r*Ktot + c*4));
        }
        CPCOMMIT();
    };

    load(0); load(1); load(2);

    for (int cc = 0; cc < nch; cc++){
        const int rem = nch - 1 - cc;
        if (rem >= 2)      CPWAIT(2);
        else if (rem == 1) CPWAIT(1);
        else               CPWAIT(0);
        __syncthreads();
        if (cc + 3 < nch) load(cc + 3);

        const int s = cc % STAGES;
        const uint32_t aBase = smem_b + s*A_ST + aoff;
        const uint32_t bBase = smem_b + STAGES*A_ST + s*B_ST + boff;
#pragma unroll
        for (int kk = 0; kk < 4; kk++){
            uint32_t a[4][4], bf[4][4];
#pragma unroll
            for (int mi = 0; mi < 4; mi++)
                LDSM4(a[mi][0], a[mi][1], a[mi][2], a[mi][3],
                      aBase + mi*(16*TSTR*4) + kk*32);
#pragma unroll
            for (int np = 0; np < 4; np++)
                LDSM4(bf[np][0], bf[np][1], bf[np][2], bf[np][3],
                      bBase + np*(16*TSTR*4) + kk*32);
#pragma unroll
            for (int np = 0; np < 4; np++)
#pragma unroll
                for (int mi = 0; mi < 4; mi++){
                    mma8(d[mi][2*np],   a[mi], bf[np][0], bf[np][1]);
                    mma8(d[mi][2*np+1], a[mi], bf[np][2], bf[np][3]);
                }
        }
    }

    // ---------------- epilogue ----------------
    const int lc2 = lc * 2;

    if (MODE != 3){
        float bv0[8], bv1[8], sc0[8], sc1[8], sh0[8], sh1[8];
#pragma unroll
        for (int ni = 0; ni < 8; ni++){
            const int gc = n0 + wn*64 + ni*8 + lc2;
            if (MODE <= 1){ bv0[ni] = bias[gc]; bv1[ni] = bias[gc+1]; }
            if (MODE == 2){
                float i0 = gg[gc]   * rsqrtf(vv[gc]   + EPSF);
                float i1 = gg[gc+1] * rsqrtf(vv[gc+1] + EPSF);
                sc0[ni] = i0; sh0[ni] = bb[gc]   - mm[gc]  *i0;
                sc1[ni] = i1; sh1[ni] = bb[gc+1] - mm[gc+1]*i1;
            }
        }
        const int bidx  = (MODE == 1) ? m0 / HW : 0;
        const int pixl0 = (MODE == 1) ? m0 - bidx*HW : 0;
        const float* xb = (MODE == 1) ? res + (size_t)bidx*C_*HW : (const float*)0;
#pragma unroll
        for (int mi = 0; mi < 4; mi++){
#pragma unroll
            for (int rr = 0; rr < 2; rr++){
                const int rl = wm*64 + mi*16 + lr + rr*8;
                const int r  = m0 + rl;
                float* crow = Cp + (size_t)r*Cstride + n0 + wn*64;
                float* crow2 = (MODE == 1) ? Cp2 + (size_t)r*256 + n0 + wn*64 : (float*)0;
                const int pixl = pixl0 + rl;
#pragma unroll
                for (int ni = 0; ni < 8; ni++){
                    const int c = ni*8 + lc2;
                    float v0 = d[mi][ni][rr*2+0];
                    float v1 = d[mi][ni][rr*2+1];
                    if (MODE == 0){
                        v0 += bv0[ni]; v1 += bv1[ni];
                        *(float2*)(crow + c) = make_float2(v0, v1);
                    } else if (MODE == 1){
                        const int gc = n0 + wn*64 + c;
                        v0 += bv0[ni] + xb[(size_t)gc*HW + pixl];
                        v1 += bv1[ni] + xb[(size_t)(gc+1)*HW + pixl];
                        *(float2*)(crow2 + c) = make_float2(v0, v1);
                        *(float2*)(crow  + c) = make_float2(rna(v0), rna(v1));
                    } else { // MODE 2
                        v0 = v0*sc0[ni] + sh0[ni];
                        v1 = v1*sc1[ni] + sh1[ni];
                        v0 = v0 * __frcp_rn(1.f + __expf(-v0));
                        v1 = v1 * __frcp_rn(1.f + __expf(-v1));
                        *(float2*)(crow + c) = make_float2(rna(v0), rna(v1));
                    }
                }
            }
        }
    } else {
        // MODE 3: bn2 + residual, smem-transposed coalesced store to [b][c][hw]
        __syncthreads();
        float* stg = smemf + wid * (64*65);
#pragma unroll
        for (int ni = 0; ni < 8; ni++){
            const int gc = n0 + wn*64 + ni*8 + lc2;
            const float i0 = gg[gc]   * rsqrtf(vv[gc]   + EPSF);
            const float i1 = gg[gc+1] * rsqrtf(vv[gc+1] + EPSF);
            const float s0 = bb[gc]   - mm[gc]  *i0;
            const float s1 = bb[gc+1] - mm[gc+1]*i1;
#pragma unroll
            for (int mi = 0; mi < 4; mi++){
#pragma unroll
                for (int rr = 0; rr < 2; rr++){
                    const int lrow = mi*16 + lr + rr*8;
                    const int grow = m0 + wm*64 + lrow;
                    const float* rp = res + (size_t)grow*256 + gc;
                    stg[lrow*65 + ni*8 + lc2]     = d[mi][ni][rr*2+0]*i0 + s0 + rp[0];
                    stg[lrow*65 + ni*8 + lc2 + 1] = d[mi][ni][rr*2+1]*i1 + s1 + rp[1];
                }
            }
        }
        __syncwarp();
        const int pix0 = m0 + wm*64;
        const int bidx = pix0 / HW;
        const int pixl = pix0 - bidx*HW;
        float* ob = Cp + (size_t)bidx*C_*HW + pixl;
#pragma unroll
        for (int n = 0; n < 64; n++){
            const int gc = n0 + wn*64 + n;
            ob[(size_t)gc*HW + lane]      = stg[lane*65 + n];
            ob[(size_t)gc*HW + lane + 32] = stg[(lane+32)*65 + n];
        }
    }
}

// ---------------- transpose x [B][C][HW] -> xT (tf32-rounded) ----------------
__global__ __launch_bounds__(256) void transpose_k(const float* __restrict__ x,
                                                   float* __restrict__ xT)
{
    __shared__ float t[32][33];
    const int b = blockIdx.z;
    const int hw0 = blockIdx.x * 32, c0 = blockIdx.y * 32;
    const int tx = threadIdx.x, ty = threadIdx.y;
#pragma unroll
    for (int i = 0; i < 4; i++){
        int c = c0 + ty + i*8;
        t[ty + i*8][tx] = x[(size_t)b*C_*HW + (size_t)c*HW + hw0 + tx];
    }
    __syncthreads();
#pragma unroll
    for (int i = 0; i < 4; i++){
        int hw = hw0 + ty + i*8;
        xT[(size_t)(b*HW + hw)*256 + c0 + tx] = rna(t[tx][ty + i*8]);
    }
}

// ---------------- round weights ----------------
__global__ __launch_bounds__(256) void roundw_k(
    const float* __restrict__ qkvw, const float* __restrict__ projw,
    const float* __restrict__ w1, const float* __restrict__ w2, float* __restrict__ gw)
{
    int i = blockIdx.x * 256 + threadIdx.x;
    float v;
    if (i < 196608)      v = qkvw[i];
    else if (i < 262144) v = projw[i - 196608];
    else if (i < 393216) v = w1[i - 262144];
    else                 v = w2[i - 393216];
    gw[i] = rna(v);
}

// ---------------- fused attention + fc-mix + LayerNorm ----------------
__global__ __launch_bounds__(256) void attn_ln_k(
    const float* __restrict__ qkv,
    const float* __restrict__ fcw, const float* __restrict__ fcb,
    const float* __restrict__ lng, const float* __restrict__ lnb,
    float* __restrict__ y2)
{
    __shared__ float sOut[1024];      // [4 pixels][4 dil][64 ch]
    __shared__ float ssum[8], ssq[8];

    const int tid  = threadIdx.x;
    const int wid  = tid >> 5;
    const int lane = tid & 31;
    const int pp   = wid >> 1;
    const int dp   = wid & 1;
    const int dil  = dp*2 + (lane >> 4);
    const int c0   = (lane & 15) * 4;
    const int pix  = blockIdx.x * 4 + pp;
    const int b    = pix / HW;
    const int pixl = pix - b * HW;
    const int y    = pixl / Ww;
    const int x    = pixl - y * Ww;
    const int r    = 1 << dil;

    const float* base = qkv + (size_t)b * HW * 768 + dil*64 + c0;

    int offs[9]; unsigned vm = 0;
#pragma unroll
    for (int j = 0; j < 9; j++){
        const int yy = y + (j/3 - 1) * r;
        const int xx = x + (j%3 - 1) * r;
        offs[j] = (yy*Ww + xx) * 768;
        if ((unsigned)yy < (unsigned)Hh && (unsigned)xx < (unsigned)Ww) vm |= 1u << j;
    }

    const float4 q = *(const float4*)(base + pixl*768);

    float sc[9];
#pragma unroll
    for (int j = 0; j < 9; j++){
        float s = 0.f;
        if (vm & (1u << j)){
            const float4 kv = *(const float4*)(base + offs[j] + 256);
            s = q.x*kv.x + q.y*kv.y + q.z*kv.z + q.w*kv.w;
        }
#pragma unroll
        for (int o = 8; o > 0; o >>= 1) s += __shfl_xor_sync(0xffffffffu, s, o);
        sc[j] = s * 0.125f;
    }

    float mx = sc[0];
#pragma unroll
    for (int j = 1; j < 9; j++) mx = fmaxf(mx, sc[j]);
    float p[9], sum = 0.f;
#pragma unroll
    for (int j = 0; j < 9; j++){ p[j] = __expf(sc[j] - mx); sum += p[j]; }
    const float inv = __frcp_rn(sum);

    float a0 = 0.f, a1 = 0.f, a2 = 0.f, a3 = 0.f;
#pragma unroll
    for (int j = 0; j < 9; j++){
        if (vm & (1u << j)){
            const float4 vv = *(const float4*)(base + offs[j] + 512);
            a0 += p[j] * vv.x;
            a1 += p[j] * vv.y;
            a2 += p[j] * vv.z;
            a3 += p[j] * vv.w;
        }
    }
    *(float4*)(sOut + pp*256 + dil*64 + c0) = make_float4(a0*inv, a1*inv, a2*inv, a3*inv);
    __syncthreads();

    const int t = tid >> 6;
    const int c = tid & 63;
    const int w = tid >> 5;
#pragma unroll
    for (int qq = 0; qq < 4; qq++){
        const float* sp = sOut + qq*256;
        const float s0 = sp[c], s1 = sp[64 + c], s2 = sp[128 + c], s3 = sp[192 + c];
        const float own = (t == 0) ? s0 : (t == 1) ? s1 : (t == 2) ? s2 : s3;
        float f = fcw[t*4+0]*s0 + fcw[t*4+1]*s1 + fcw[t*4+2]*s2 + fcw[t*4+3]*s3
                  + fcb[t] + own;

        float sm = f, sq = f*f;
#pragma unroll
        for (int o = 16; o > 0; o >>= 1){
            sm += __shfl_xor_sync(0xffffffffu, sm, o);
            sq += __shfl_xor_sync(0xffffffffu, sq, o);
        }
        if ((tid & 31) == 0){ ssum[w] = sm; ssq[w] = sq; }
        __syncthreads();
        const float tot  = ssum[2*t] + ssum[2*t+1];
        const float totq = ssq[2*t]  + ssq[2*t+1];
        const float mu  = tot * (1.f/64.f);
        const float var = totq * (1.f/64.f) - mu*mu;
        const float yv = (f - mu) * rsqrtf(var + EPSF) * lng[c] + lnb[c];
        y2[(size_t)(blockIdx.x*4 + qq)*256 + tid] = rna(yv);
        __syncthreads();
    }
}

// ---------------- launch ----------------
extern "C" void kernel_launch(void* const* d_in, const int* in_sizes, int n_in,
                              void* d_out, int out_size)
{
    const float* x      = (const float*)d_in[0];
    const float* qkv_w  = (const float*)d_in[1];
    const float* qkv_b  = (const float*)d_in[2];
    const float* fc_w   = (const float*)d_in[3];
    const float* fc_b   = (const float*)d_in[4];
    const float* ln_g   = (const float*)d_in[5];
    const float* ln_b   = (const float*)d_in[6];
    const float* proj_w = (const float*)d_in[7];
    const float* proj_b = (const float*)d_in[8];
    const float* w1     = (const float*)d_in[9];
    const float* bn1_g  = (const float*)d_in[10];
    const float* bn1_b  = (const float*)d_in[11];
    const float* bn1_m  = (const float*)d_in[12];
    const float* bn1_v  = (const float*)d_in[13];
    const float* w2     = (const float*)d_in[14];
    const float* bn2_g  = (const float*)d_in[15];
    const float* bn2_b  = (const float*)d_in[16];
    const float* bn2_m  = (const float*)d_in[17];
    const float* bn2_v  = (const float*)d_in[18];
    float* out = (float*)d_out;

    float *xT, *qkv, *y2, *x1r, *x1f, *hb, *gw;
    cudaGetSymbolAddress((void**)&xT,  g_xT);
    cudaGetSymbolAddress((void**)&qkv, g_qkv);
    cudaGetSymbolAddress((void**)&y2,  g_y2);
    cudaGetSymbolAddress((void**)&x1r, g_x1r);
    cudaGetSymbolAddress((void**)&x1f, g_x1f);
    cudaGetSymbolAddress((void**)&hb,  g_h);
    cudaGetSymbolAddress((void**)&gw,  g_w);

    cudaFuncSetAttribute(gemm_mma<0>, cudaFuncAttributeMaxDynamicSharedMemorySize, SMEM_BYTES);
    cudaFuncSetAttribute(gemm_mma<1>, cudaFuncAttributeMaxDynamicSharedMemorySize, SMEM_BYTES);
    cudaFuncSetAttribute(gemm_mma<2>, cudaFuncAttributeMaxDynamicSharedMemorySize, SMEM_BYTES);
    cudaFuncSetAttribute(gemm_mma<3>, cudaFuncAttributeMaxDynamicSharedMemorySize, SMEM_BYTES);

    roundw_k<<<2048, 256>>>(qkv_w, proj_w, w1, w2, gw);
    transpose_k<<<dim3(HW/32, C_/32, B_), dim3(32, 8)>>>(x, xT);

    // 1) qkv = xT @ qkv_w^T + b : [51200][768]
    gemm_mma<0><<<dim3(3, 400), 256, SMEM_BYTES>>>(
        xT, gw, qkv, nullptr, 256, 768, qkv_b, nullptr, nullptr, nullptr, nullptr, nullptr);

    // 2+3) attention + fc mix + LN (fused)
    attn_ln_k<<<NPIX/4, 256>>>(qkv, fc_w, fc_b, ln_g, ln_b, y2);

    // 4) x1 = y2 @ proj_w^T + proj_b + x
    gemm_mma<1><<<dim3(1, 400), 256, SMEM_BYTES>>>(
        y2, gw + 196608, x1r, x1f, 256, 256, proj_b, x, nullptr, nullptr, nullptr, nullptr);

    // 5) h = silu(bn1(x1 @ w1^T)) : [51200][512]
    gemm_mma<2><<<dim3(2, 400), 256, SMEM_BYTES>>>(
        x1r, gw + 262144, hb, nullptr, 256, 512, nullptr, nullptr, bn1_g, bn1_b, bn1_m, bn1_v);

    // 6) out = x1 + bn2(h @ w2^T) -> [B][C][HW]
    gemm_mma<3><<<dim3(1, 400), 256, SMEM_BYTES>>>(
        hb, gw + 393216, out, nullptr, 512, 256, nullptr, x1f, bn2_g, bn2_b, bn2_m, bn2_v);
}

// round 8
// speedup vs baseline: 1.5884x; 1.5884x over previous
#include <cuda_runtime.h>
#include <cuda_fp16.h>
#include <cstdint>
#include <math.h>

#define B_  8
#define C_  256
#define Hh  80
#define Ww  80
#define HW  6400
#define NPIX 51200
#define EPSF 1e-5f

#define KC 32
#define STAGES 4
#define TSTRH 40                 // smem row stride in halfs (80B): LDSM conflict-free
#define ST_B (128*TSTRH*2)       // 10240 B per operand stage
#define SMEM_BYTES (STAGES*2*ST_B)   // 81920 B

// ---------------- scratch ----------------
__device__ __half g_xT [(size_t)NPIX*256];
__device__ __half g_qkv[(size_t)NPIX*768];
__device__ __half g_y2 [(size_t)NPIX*256];
__device__ __half g_x1h[(size_t)NPIX*256];
__device__ float  g_x1f[(size_t)NPIX*256];
__device__ __half g_h  [(size_t)NPIX*512];
__device__ __half g_w  [524288];

// ---------------- helpers ----------------
__device__ __forceinline__ uint32_t s2u(const void* p){
    uint32_t a; asm("{ .reg .u64 t; cvta.to.shared.u64 t, %1; cvt.u32.u64 %0, t; }" : "=r"(a) : "l"(p)); return a;
}
#define CPA16(d,s) asm volatile("cp.async.cg.shared.global [%0], [%1], 16;" :: "r"(d), "l"(s))
#define CPCOMMIT() asm volatile("cp.async.commit_group;" ::: "memory")
#define CPWAIT(n)  asm volatile("cp.async.wait_group %0;" :: "n"(n) : "memory")
#define LDSM4(r0,r1,r2,r3,a) \
    asm volatile("ldmatrix.sync.aligned.m8n8.x4.shared.b16 {%0,%1,%2,%3}, [%4];" \
        : "=r"(r0), "=r"(r1), "=r"(r2), "=r"(r3) : "r"(a))

__device__ __forceinline__ void mma16(float* d, const uint32_t* a, uint32_t b0, uint32_t b1){
    asm volatile("mma.sync.aligned.m16n8k16.row.col.f32.f16.f16.f32 "
        "{%0,%1,%2,%3}, {%4,%5,%6,%7}, {%8,%9}, {%0,%1,%2,%3};"
        : "+f"(d[0]), "+f"(d[1]), "+f"(d[2]), "+f"(d[3])
        : "r"(a[0]), "r"(a[1]), "r"(a[2]), "r"(a[3]), "r"(b0), "r"(b1));
}

// ---------------- fp16 mma.sync GEMM, 128x128 tile, 4-stage single-sync ----------------
// D[pix,n] = A[pix,:] . Bw[n,:]  (A,Bw half; accum fp32)
// MODE 0: Ch = acc + bias[n]                      -> qkv half (Cstride 768)
// MODE 1: Ch = half(acc+bias+resx), Cf = full     -> x1h / x1f  (resx = x[b][c][hw] fp32)
// MODE 2: Ch = half(silu(acc*sc+sh))              -> h half (Cstride 512)
// MODE 3: Cf = acc*sc+sh + res -> out[b][n][pixl] (smem-staged transposed store; res fp32)
template<int MODE>
__global__ __launch_bounds__(256, 2) void gemm_mma(
    const __half* __restrict__ A, const __half* __restrict__ Bw,
    __half* __restrict__ Ch, float* __restrict__ Cf, int Ktot, int Cstride,
    const float* __restrict__ bias, const float* __restrict__ res,
    const float* __restrict__ gg, const float* __restrict__ bb,
    const float* __restrict__ mm, const float* __restrict__ vv)
{
    extern __shared__ float smemf[];
    const uint32_t smem_b = s2u(smemf);

    const int tid  = threadIdx.x;
    const int wid  = tid >> 5;
    const int lane = tid & 31;
    const int wm   = wid & 1;         // 2 warps in M (64 rows)
    const int wn   = wid >> 1;        // 4 warps in N (32 cols)
    const int lr   = lane >> 2;
    const int lc   = lane & 3;
    const int m0   = blockIdx.y * 128;
    const int n0   = blockIdx.x * 128;

    // LDSM per-thread byte offsets within a stage
    const uint32_t aoff = (uint32_t)(((wm*64 + ((lane>>3)&1)*8 + (lane&7))*TSTRH + (lane>>4)*8) * 2);
    const uint32_t boff = (uint32_t)(((wn*32 + (lane>>4)*8 + (lane&7))*TSTRH + ((lane>>3)&1)*8) * 2);

    float d[4][4][4];
#pragma unroll
    for (int i = 0; i < 4; i++)
#pragma unroll
        for (int j = 0; j < 4; j++)
#pragma unroll
            for (int e = 0; e < 4; e++) d[i][j][e] = 0.f;

    const int nch = Ktot / KC;

    auto load = [&](int cc){
        const int s = cc % STAGES;
        const __half* Ab = A + (size_t)m0 * Ktot + cc*KC;
        const uint32_t da = smem_b + (2*s)*ST_B;
#pragma unroll
        for (int t = 0; t < 2; t++){
            int i = tid + t*256;
            int r = i >> 2, c = i & 3;
            CPA16(da + r*TSTRH*2 + c*16, (const void*)(Ab + (size_t)r*Ktot + c*8));
        }
        const __half* Bb = Bw + (size_t)n0 * Ktot + cc*KC;
        const uint32_t db = smem_b + (2*s+1)*ST_B;
#pragma unroll
        for (int t = 0; t < 2; t++){
            int i = tid + t*256;
            int r = i >> 2, c = i & 3;
            CPA16(db + r*TSTRH*2 + c*16, (const void*)(Bb + (size_t)r*Ktot + c*8));
        }
        CPCOMMIT();
    };

    load(0); load(1); load(2);

    for (int cc = 0; cc < nch; cc++){
        const int rem = nch - 1 - cc;
        if (rem >= 2)      CPWAIT(2);
        else if (rem == 1) CPWAIT(1);
        else               CPWAIT(0);
        __syncthreads();
        if (cc + 3 < nch) load(cc + 3);

        const int s = cc % STAGES;
        const uint32_t aBase = smem_b + (2*s)*ST_B + aoff;
        const uint32_t bBase = smem_b + (2*s+1)*ST_B + boff;
#pragma unroll
        for (int kk = 0; kk < 2; kk++){
            uint32_t a[4][4], bf[2][4];
#pragma unroll
            for (int mi = 0; mi < 4; mi++)
                LDSM4(a[mi][0], a[mi][1], a[mi][2], a[mi][3],
                      aBase + mi*(16*TSTRH*2) + kk*32);
#pragma unroll
            for (int np = 0; np < 2; np++)
                LDSM4(bf[np][0], bf[np][1], bf[np][2], bf[np][3],
                      bBase + np*(16*TSTRH*2) + kk*32);
#pragma unroll
            for (int np = 0; np < 2; np++)
#pragma unroll
                for (int mi = 0; mi < 4; mi++){
                    mma16(d[mi][2*np],   a[mi], bf[np][0], bf[np][1]);
                    mma16(d[mi][2*np+1], a[mi], bf[np][2], bf[np][3]);
                }
        }
    }

    // ---------------- epilogue ----------------
    const int lc2 = lc * 2;

    if (MODE != 3){
        float bv0[4], bv1[4], sc0[4], sc1[4], sh0[4], sh1[4];
#pragma unroll
        for (int ni = 0; ni < 4; ni++){
            const int gc = n0 + wn*32 + ni*8 + lc2;
            if (MODE <= 1){ bv0[ni] = bias[gc]; bv1[ni] = bias[gc+1]; }
            if (MODE == 2){
                float i0 = gg[gc]   * rsqrtf(vv[gc]   + EPSF);
                float i1 = gg[gc+1] * rsqrtf(vv[gc+1] + EPSF);
                sc0[ni] = i0; sh0[ni] = bb[gc]   - mm[gc]  *i0;
                sc1[ni] = i1; sh1[ni] = bb[gc+1] - mm[gc+1]*i1;
            }
        }
        const int bidx  = (MODE == 1) ? m0 / HW : 0;
        const int pixl0 = (MODE == 1) ? m0 - bidx*HW : 0;
        const float* xb = (MODE == 1) ? res + (size_t)bidx*C_*HW : (const float*)0;
#pragma unroll
        for (int mi = 0; mi < 4; mi++){
#pragma unroll
            for (int rr = 0; rr < 2; rr++){
                const int rl = wm*64 + mi*16 + lr + rr*8;
                const int r  = m0 + rl;
                __half* crow = Ch + (size_t)r*Cstride + n0 + wn*32;
                float* crow2 = (MODE == 1) ? Cf + (size_t)r*256 + n0 + wn*32 : (float*)0;
                const int pixl = pixl0 + rl;
#pragma unroll
                for (int ni = 0; ni < 4; ni++){
                    const int c = ni*8 + lc2;
                    float v0 = d[mi][ni][rr*2+0];
                    float v1 = d[mi][ni][rr*2+1];
                    if (MODE == 0){
                        v0 += bv0[ni]; v1 += bv1[ni];
                        *(__half2*)(crow + c) = __floats2half2_rn(v0, v1);
                    } else if (MODE == 1){
                        const int gc = n0 + wn*32 + c;
                        v0 += bv0[ni] + xb[(size_t)gc*HW + pixl];
                        v1 += bv1[ni] + xb[(size_t)(gc+1)*HW + pixl];
                        *(float2*)(crow2 + c) = make_float2(v0, v1);
                        *(__half2*)(crow + c) = __floats2half2_rn(v0, v1);
                    } else { // MODE 2
                        v0 = v0*sc0[ni] + sh0[ni];
                        v1 = v1*sc1[ni] + sh1[ni];
                        v0 = v0 * __frcp_rn(1.f + __expf(-v0));
                        v1 = v1 * __frcp_rn(1.f + __expf(-v1));
                        *(__half2*)(crow + c) = __floats2half2_rn(v0, v1);
                    }
                }
            }
        }
    } else {
        // MODE 3: bn2 + residual, smem-transposed coalesced store to [b][c][hw]
        __syncthreads();
        float* stg = smemf + wid * (64*33);
#pragma unroll
        for (int ni = 0; ni < 4; ni++){
            const int gc = n0 + wn*32 + ni*8 + lc2;
            const float i0 = gg[gc]   * rsqrtf(vv[gc]   + EPSF);
            const float i1 = gg[gc+1] * rsqrtf(vv[gc+1] + EPSF);
            const float s0 = bb[gc]   - mm[gc]  *i0;
            const float s1 = bb[gc+1] - mm[gc+1]*i1;
#pragma unroll
            for (int mi = 0; mi < 4; mi++){
#pragma unroll
                for (int rr = 0; rr < 2; rr++){
                    const int lrow = mi*16 + lr + rr*8;
                    const int grow = m0 + wm*64 + lrow;
                    const float* rp = res + (size_t)grow*256 + gc;
                    stg[lrow*33 + ni*8 + lc2]     = d[mi][ni][rr*2+0]*i0 + s0 + rp[0];
                    stg[lrow*33 + ni*8 + lc2 + 1] = d[mi][ni][rr*2+1]*i1 + s1 + rp[1];
                }
            }
        }
        __syncwarp();
        const int pix0 = m0 + wm*64;
        const int bidx = pix0 / HW;
        const int pixl = pix0 - bidx*HW;
        float* ob = Cf + (size_t)bidx*C_*HW + pixl;
#pragma unroll
        for (int n = 0; n < 32; n++){
            const int gc = n0 + wn*32 + n;
            ob[(size_t)gc*HW + lane]      = stg[lane*33 + n];
            ob[(size_t)gc*HW + lane + 32] = stg[(lane+32)*33 + n];
        }
    }
}

// ---------------- transpose x [B][C][HW] -> xT half ----------------
__global__ __launch_bounds__(256) void transpose_k(const float* __restrict__ x,
                                                   __half* __restrict__ xT)
{
    __shared__ float t[32][33];
    const int b = blockIdx.z;
    const int hw0 = blockIdx.x * 32, c0 = blockIdx.y * 32;
    const int tx = threadIdx.x, ty = threadIdx.y;
#pragma unroll
    for (int i = 0; i < 4; i++){
        int c = c0 + ty + i*8;
        t[ty + i*8][tx] = x[(size_t)b*C_*HW + (size_t)c*HW + hw0 + tx];
    }
    __syncthreads();
#pragma unroll
    for (int i = 0; i < 4; i++){
        int hw = hw0 + ty + i*8;
        xT[(size_t)(b*HW + hw)*256 + c0 + tx] = __float2half_rn(t[tx][ty + i*8]);
    }
}

// ---------------- convert weights to half ----------------
__global__ __launch_bounds__(256) void convw_k(
    const float* __restrict__ qkvw, const float* __restrict__ projw,
    const float* __restrict__ w1, const float* __restrict__ w2, __half* __restrict__ gw)
{
    int i = blockIdx.x * 256 + threadIdx.x;
    float v;
    if (i < 196608)      v = qkvw[i];
    else if (i < 262144) v = projw[i - 196608];
    else if (i < 393216) v = w1[i - 262144];
    else                 v = w2[i - 393216];
    gw[i] = __float2half_rn(v);
}

// ---------------- fused attention + fc-mix + LayerNorm (half qkv) ----------------
__global__ __launch_bounds__(256) void attn_ln_k(
    const __half* __restrict__ qkv,
    const float* __restrict__ fcw, const float* __restrict__ fcb,
    const float* __restrict__ lng, const float* __restrict__ lnb,
    __half* __restrict__ y2)
{
    __shared__ float sOut[1024];      // [4 pixels][4 dil][64 ch]
    __shared__ float ssum[8], ssq[8];

    const int tid  = threadIdx.x;
    const int wid  = tid >> 5;
    const int lane = tid & 31;
    const int pp   = wid >> 1;
    const int dp   = wid & 1;
    const int dil  = dp*2 + (lane >> 4);
    const int c0   = (lane & 15) * 4;
    const int pix  = blockIdx.x * 4 + pp;
    const int b    = pix / HW;
    const int pixl = pix - b * HW;
    const int y    = pixl / Ww;
    const int x    = pixl - y * Ww;
    const int r    = 1 << dil;

    const __half* base = qkv + (size_t)b * HW * 768 + dil*64 + c0;

    int offs[9]; unsigned vm = 0;
#pragma unroll
    for (int j = 0; j < 9; j++){
        const int yy = y + (j/3 - 1) * r;
        const int xx = x + (j%3 - 1) * r;
        offs[j] = (yy*Ww + xx) * 768;
        if ((unsigned)yy < (unsigned)Hh && (unsigned)xx < (unsigned)Ww) vm |= 1u << j;
    }

    uint2 qu = *(const uint2*)(base + (size_t)pixl*768);
    const float2 q01 = __half22float2(*(__half2*)&qu.x);
    const float2 q23 = __half22float2(*(__half2*)&qu.y);

    float sc[9];
#pragma unroll
    for (int j = 0; j < 9; j++){
        float s = 0.f;
        if (vm & (1u << j)){
            uint2 ku = *(const uint2*)(base + offs[j] + 256);
            const float2 k01 = __half22float2(*(__half2*)&ku.x);
            const float2 k23 = __half22float2(*(__half2*)&ku.y);
            s = q01.x*k01.x + q01.y*k01.y + q23.x*k23.x + q23.y*k23.y;
        }
#pragma unroll
        for (int o = 8; o > 0; o >>= 1) s += __shfl_xor_sync(0xffffffffu, s, o);
        sc[j] = s * 0.125f;
    }

    float mx = sc[0];
#pragma unroll
    for (int j = 1; j < 9; j++) mx = fmaxf(mx, sc[j]);
    float p[9], sum = 0.f;
#pragma unroll
    for (int j = 0; j < 9; j++){ p[j] = __expf(sc[j] - mx); sum += p[j]; }
    const float inv = __frcp_rn(sum);

    float a0 = 0.f, a1 = 0.f, a2 = 0.f, a3 = 0.f;
#pragma unroll
    for (int j = 0; j < 9; j++){
        if (vm & (1u << j)){
            uint2 vu = *(const uint2*)(base + offs[j] + 512);
            const float2 v01 = __half22float2(*(__half2*)&vu.x);
            const float2 v23 = __half22float2(*(__half2*)&vu.y);
            a0 += p[j] * v01.x;
            a1 += p[j] * v01.y;
            a2 += p[j] * v23.x;
            a3 += p[j] * v23.y;
        }
    }
    *(float4*)(sOut + pp*256 + dil*64 + c0) = make_float4(a0*inv, a1*inv, a2*inv, a3*inv);
    __syncthreads();

    const int t = tid >> 6;
    const int c = tid & 63;
    const int w = tid >> 5;
#pragma unroll
    for (int qq = 0; qq < 4; qq++){
        const float* sp = sOut + qq*256;
        const float s0 = sp[c], s1 = sp[64 + c], s2 = sp[128 + c], s3 = sp[192 + c];
        const float own = (t == 0) ? s0 : (t == 1) ? s1 : (t == 2) ? s2 : s3;
        float f = fcw[t*4+0]*s0 + fcw[t*4+1]*s1 + fcw[t*4+2]*s2 + fcw[t*4+3]*s3
                  + fcb[t] + own;

        float sm = f, sq = f*f;
#pragma unroll
        for (int o = 16; o > 0; o >>= 1){
            sm += __shfl_xor_sync(0xffffffffu, sm, o);
            sq += __shfl_xor_sync(0xffffffffu, sq, o);
        }
        if ((tid & 31) == 0){ ssum[w] = sm; ssq[w] = sq; }
        __syncthreads();
        const float tot  = ssum[2*t] + ssum[2*t+1];
        const float totq = ssq[2*t]  + ssq[2*t+1];
        const float mu  = tot * (1.f/64.f);
        const float var = totq * (1.f/64.f) - mu*mu;
        const float yv = (f - mu) * rsqrtf(var + EPSF) * lng[c] + lnb[c];
        y2[(size_t)(blockIdx.x*4 + qq)*256 + tid] = __float2half_rn(yv);
        __syncthreads();
    }
}

// ---------------- launch ----------------
extern "C" void kernel_launch(void* const* d_in, const int* in_sizes, int n_in,
                              void* d_out, int out_size)
{
    const float* x      = (const float*)d_in[0];
    const float* qkv_w  = (const float*)d_in[1];
    const float* qkv_b  = (const float*)d_in[2];
    const float* fc_w   = (const float*)d_in[3];
    const float* fc_b   = (const float*)d_in[4];
    const float* ln_g   = (const float*)d_in[5];
    const float* ln_b   = (const float*)d_in[6];
    const float* proj_w = (const float*)d_in[7];
    const float* proj_b = (const float*)d_in[8];
    const float* w1     = (const float*)d_in[9];
    const float* bn1_g  = (const float*)d_in[10];
    const float* bn1_b  = (const float*)d_in[11];
    const float* bn1_m  = (const float*)d_in[12];
    const float* bn1_v  = (const float*)d_in[13];
    const float* w2     = (const float*)d_in[14];
    const float* bn2_g  = (const float*)d_in[15];
    const float* bn2_b  = (const float*)d_in[16];
    const float* bn2_m  = (const float*)d_in[17];
    const float* bn2_v  = (const float*)d_in[18];
    float* out = (float*)d_out;

    __half *xT, *qkv, *y2, *x1h, *hb, *gw;
    float *x1f;
    cudaGetSymbolAddress((void**)&xT,  g_xT);
    cudaGetSymbolAddress((void**)&qkv, g_qkv);
    cudaGetSymbolAddress((void**)&y2,  g_y2);
    cudaGetSymbolAddress((void**)&x1h, g_x1h);
    cudaGetSymbolAddress((void**)&x1f, g_x1f);
    cudaGetSymbolAddress((void**)&hb,  g_h);
    cudaGetSymbolAddress((void**)&gw,  g_w);

    cudaFuncSetAttribute(gemm_mma<0>, cudaFuncAttributeMaxDynamicSharedMemorySize, SMEM_BYTES);
    cudaFuncSetAttribute(gemm_mma<1>, cudaFuncAttributeMaxDynamicSharedMemorySize, SMEM_BYTES);
    cudaFuncSetAttribute(gemm_mma<2>, cudaFuncAttributeMaxDynamicSharedMemorySize, SMEM_BYTES);
    cudaFuncSetAttribute(gemm_mma<3>, cudaFuncAttributeMaxDynamicSharedMemorySize, SMEM_BYTES);

    convw_k<<<2048, 256>>>(qkv_w, proj_w, w1, w2, gw);
    transpose_k<<<dim3(HW/32, C_/32, B_), dim3(32, 8)>>>(x, xT);

    // 1) qkv = xT @ qkv_w^T + b : [51200][768] half
    gemm_mma<0><<<dim3(6, 400), 256, SMEM_BYTES>>>(
        xT, gw, qkv, nullptr, 256, 768, qkv_b, nullptr, nullptr, nullptr, nullptr, nullptr);

    // 2+3) attention + fc mix + LN (fused) -> y2 half
    attn_ln_k<<<NPIX/4, 256>>>(qkv, fc_w, fc_b, ln_g, ln_b, y2);

    // 4) x1 = y2 @ proj_w^T + proj_b + x -> x1h (half) / x1f (float)
    gemm_mma<1><<<dim3(2, 400), 256, SMEM_BYTES>>>(
        y2, gw + 196608, x1h, x1f, 256, 256, proj_b, x, nullptr, nullptr, nullptr, nullptr);

    // 5) h = silu(bn1(x1 @ w1^T)) : [51200][512] half
    gemm_mma<2><<<dim3(4, 400), 256, SMEM_BYTES>>>(
        x1h, gw + 262144, hb, nullptr, 256, 512, nullptr, nullptr, bn1_g, bn1_b, bn1_m, bn1_v);

    // 6) out = x1 + bn2(h @ w2^T) -> [B][C][HW] float
    gemm_mma<3><<<dim3(2, 400), 256, SMEM_BYTES>>>(
        hb, gw + 393216, nullptr, out, 512, 256, nullptr, x1f, bn2_g, bn2_b, bn2_m, bn2_v);
}